// round 11
// baseline (speedup 1.0000x reference)
#include <cuda_runtime.h>
#include <cuda_bf16.h>
#include <math.h>
#include <stdint.h>

// Problem constants
constexpr int Bsz = 32;
constexpr int Lsz = 2048;
constexpr int Hsz = 1024;

// Scratch
__device__ float g_wq[Bsz * Hsz];
__device__ float g_scores[Bsz * Lsz];
__device__ float g_weights[Bsz * Lsz];
__device__ float g_part[8][Bsz * Hsz];
__device__ __align__(16) __nv_bfloat16 g_uw_hi[Hsz * Hsz];        // ua_w hi
__device__ __align__(16) __nv_bfloat16 g_uw_lo[Hsz * Hsz];        // ua_w lo
__device__ __align__(16) __nv_bfloat16 g_k_hi[Bsz * Lsz * Hsz];   // keys hi (128MB)
__device__ __align__(16) __nv_bfloat16 g_k_lo[Bsz * Lsz * Hsz];   // keys lo (128MB)

// ---------------------------------------------------------------------------
// mma.sync / ldmatrix / cp.async helpers (sm_80+ baseline, valid on sm_100)
// ---------------------------------------------------------------------------
__device__ __forceinline__ uint32_t smem_to_u32(const void* p) {
    uint32_t a;
    asm("{ .reg .u64 t; cvta.to.shared.u64 t, %1; cvt.u32.u64 %0, t; }" : "=r"(a) : "l"(p));
    return a;
}
__device__ __forceinline__ void ldsm_x4(uint32_t* r, uint32_t addr) {
    asm volatile("ldmatrix.sync.aligned.m8n8.x4.shared.b16 {%0,%1,%2,%3}, [%4];"
        : "=r"(r[0]), "=r"(r[1]), "=r"(r[2]), "=r"(r[3]) : "r"(addr));
}
__device__ __forceinline__ void mma_bf16(float* c, const uint32_t* a, const uint32_t* b) {
    asm volatile("mma.sync.aligned.m16n8k16.row.col.f32.bf16.bf16.f32 "
        "{%0,%1,%2,%3}, {%4,%5,%6,%7}, {%8,%9}, {%0,%1,%2,%3};"
        : "+f"(c[0]), "+f"(c[1]), "+f"(c[2]), "+f"(c[3])
        : "r"(a[0]), "r"(a[1]), "r"(a[2]), "r"(a[3]), "r"(b[0]), "r"(b[1]));
}
__device__ __forceinline__ void cp16(uint32_t dst, const void* src) {
    asm volatile("cp.async.cg.shared.global [%0], [%1], 16;" :: "r"(dst), "l"(src));
}
#define CP_COMMIT() asm volatile("cp.async.commit_group;" ::: "memory")
#define CP_WAIT(n)  asm volatile("cp.async.wait_group %0;" :: "n"(n) : "memory")

// ---------------------------------------------------------------------------
// Split helpers
// ---------------------------------------------------------------------------
__device__ __forceinline__ void split4(float4 v, uint2& hu, uint2& lu) {
    __nv_bfloat16 h0 = __float2bfloat16_rn(v.x);
    __nv_bfloat16 h1 = __float2bfloat16_rn(v.y);
    __nv_bfloat16 h2 = __float2bfloat16_rn(v.z);
    __nv_bfloat16 h3 = __float2bfloat16_rn(v.w);
    __nv_bfloat16 l0 = __float2bfloat16_rn(v.x - __bfloat162float(h0));
    __nv_bfloat16 l1 = __float2bfloat16_rn(v.y - __bfloat162float(h1));
    __nv_bfloat16 l2 = __float2bfloat16_rn(v.z - __bfloat162float(h2));
    __nv_bfloat16 l3 = __float2bfloat16_rn(v.w - __bfloat162float(h3));
    __nv_bfloat162 ha = __halves2bfloat162(h0, h1), hb = __halves2bfloat162(h2, h3);
    __nv_bfloat162 la = __halves2bfloat162(l0, l1), lb = __halves2bfloat162(l2, l3);
    hu = make_uint2(*reinterpret_cast<uint32_t*>(&ha), *reinterpret_cast<uint32_t*>(&hb));
    lu = make_uint2(*reinterpret_cast<uint32_t*>(&la), *reinterpret_cast<uint32_t*>(&lb));
}

__global__ __launch_bounds__(256) void presplit_uw_kernel(const float* __restrict__ ua_w)
{
    const int i4 = blockIdx.x * 256 + threadIdx.x;
    uint2 hu, lu;
    split4(((const float4*)ua_w)[i4], hu, lu);
    ((uint2*)g_uw_hi)[i4] = hu;
    ((uint2*)g_uw_lo)[i4] = lu;
}

__global__ __launch_bounds__(256) void presplit_keys_kernel(const float* __restrict__ keys)
{
    const size_t i4 = (size_t)blockIdx.x * 256 + threadIdx.x;
    uint2 hu, lu;
    split4(((const float4*)keys)[i4], hu, lu);
    ((uint2*)g_k_hi)[i4] = hu;
    ((uint2*)g_k_lo)[i4] = lu;
}

// ---------------------------------------------------------------------------
// Kernel A: wq[b,k] = query[b,:]·wa_w[k,:] + wa_b[k]
// ---------------------------------------------------------------------------
__global__ __launch_bounds__(256) void wq_kernel(
    const float* __restrict__ query, const float* __restrict__ wa_w,
    const float* __restrict__ wa_b)
{
    __shared__ __align__(16) float qs[Hsz];
    const int b = blockIdx.x;
    for (int i = threadIdx.x; i < Hsz / 4; i += blockDim.x)
        ((float4*)qs)[i] = ((const float4*)(query + (size_t)b * Hsz))[i];
    __syncthreads();

    const int warp = threadIdx.x >> 5;
    const int lane = threadIdx.x & 31;
    for (int k = warp; k < Hsz; k += 8) {
        const float4* wrow = (const float4*)(wa_w + (size_t)k * Hsz);
        float sum = 0.f;
        #pragma unroll
        for (int i = 0; i < 8; i++) {
            float4 wv = wrow[lane + 32 * i];
            float4 qv = ((const float4*)qs)[lane + 32 * i];
            sum += wv.x * qv.x + wv.y * qv.y + wv.z * qv.z + wv.w * qv.w;
        }
        #pragma unroll
        for (int off = 16; off; off >>= 1)
            sum += __shfl_down_sync(0xffffffffu, sum, off);
        if (lane == 0) g_wq[b * Hsz + k] = sum + wa_b[k];
    }
}

// ---------------------------------------------------------------------------
// Kernel B: fused scores via bf16x3 mma.sync, all-copy staging with cp.async.
// CTA = 128 l-rows x all 1024 k. 8 warps; warp w owns l-rows [w*16, w*16+16).
// kc: 4 passes of KC=256 (acc = 128 regs). h in HC=32 chunks, double-buffered.
// ---------------------------------------------------------------------------
constexpr int TM = 128;
constexpr int KC = 256;
constexpr int NT = KC / 8;      // 32 n8-tiles
constexpr int HC = 32;
constexpr int NHC = Hsz / HC;   // 32
constexpr int ROWB = 80;        // 64B data + 16B pad -> conflict-free ldsm

constexpr int SM_C   = 0;                     // wq+ua_b: 4KB
constexpr int SM_VA  = 4096;                  // va_w:    4KB
constexpr int SM_A   = 8192;                  // A: [buf][hi/lo][128*80]
constexpr int A_BUF  = TM * ROWB;             // 10240
constexpr int SM_B   = SM_A + 4 * A_BUF;      // 49152; B: [buf][hi/lo][256*80]
constexpr int B_BUF  = KC * ROWB;             // 20480
constexpr int SM_TOTAL = SM_B + 4 * B_BUF;    // 131072

__global__ __launch_bounds__(256, 1) void scores_mma_kernel(
    const float* __restrict__ ua_b,
    const float* __restrict__ va_w,
    const float* __restrict__ va_b,
    const unsigned char* __restrict__ mask)
{
    extern __shared__ __align__(128) char smem[];
    const uint32_t sbase = smem_to_u32(smem);
    const int tid  = threadIdx.x;
    const int lane = tid & 31;
    const int w    = tid >> 5;
    const int b    = blockIdx.y;
    const int l0   = blockIdx.x * TM;

    float* s_c  = (float*)(smem + SM_C);
    float* s_va = (float*)(smem + SM_VA);
    for (int i = tid; i < Hsz; i += 256) {
        s_c[i]  = g_wq[b * Hsz + i] + ua_b[i];
        s_va[i] = va_w[i];
    }

    const __nv_bfloat16* kHi = g_k_hi + ((size_t)b * Lsz + l0) * Hsz;
    const __nv_bfloat16* kLo = g_k_lo + ((size_t)b * Lsz + l0) * Hsz;

    float sc0 = 0.f, sc1 = 0.f;

    // ldmatrix per-lane addressing
    const int arow = w * 16 + (lane & 15);             // A tile row
    const int aco  = (lane >> 4) << 4;                 // A k-half byte offset
    const int bn   = (lane & 7) | ((lane >> 4) << 3);  // B row 0..15 (two n8 tiles)
    const int bco  = ((lane >> 3) & 1) << 4;           // B k-half byte offset

    // cp.async staging indices
    const int a_row = tid >> 2;
    const int a_c   = tid & 3;

    #pragma unroll 1
    for (int kc = 0; kc < 4; kc++) {
        float acc[NT][4];
        #pragma unroll
        for (int nt = 0; nt < NT; nt++)
            #pragma unroll
            for (int j = 0; j < 4; j++) acc[nt][j] = 0.f;

        // ---- issue chunk 0 into buffer 0 ----
        {
            const uint32_t A0 = sbase + SM_A;
            const uint32_t B0 = sbase + SM_B;
            #pragma unroll
            for (int p = 0; p < 2; p++) {   // A hi/lo: 128 rows x 4 x16B each
                const int row = a_row + p * 64;
                cp16(A0 + row * ROWB + a_c * 16,
                     kHi + (size_t)row * Hsz + a_c * 8);
                cp16(A0 + A_BUF + row * ROWB + a_c * 16,
                     kLo + (size_t)row * Hsz + a_c * 8);
            }
            #pragma unroll
            for (int p = 0; p < 4; p++) {   // B hi/lo: 256 rows x 4 x16B each
                const int row = a_row + p * 64;
                cp16(B0 + row * ROWB + a_c * 16,
                     g_uw_hi + (size_t)(kc * KC + row) * Hsz + a_c * 8);
                cp16(B0 + B_BUF + row * ROWB + a_c * 16,
                     g_uw_lo + (size_t)(kc * KC + row) * Hsz + a_c * 8);
            }
            CP_COMMIT();
        }

        #pragma unroll 1
        for (int hc = 0; hc < NHC; hc++) {
            const int cur = hc & 1, nxt = cur ^ 1;
            const bool pf = (hc + 1 < NHC);

            // ---- issue next chunk into other buffer ----
            if (pf) {
                const int h0 = (hc + 1) * HC;
                const uint32_t An = sbase + SM_A + nxt * (2 * A_BUF);
                const uint32_t Bn = sbase + SM_B + nxt * (2 * B_BUF);
                #pragma unroll
                for (int p = 0; p < 2; p++) {
                    const int row = a_row + p * 64;
                    cp16(An + row * ROWB + a_c * 16,
                         kHi + (size_t)row * Hsz + h0 + a_c * 8);
                    cp16(An + A_BUF + row * ROWB + a_c * 16,
                         kLo + (size_t)row * Hsz + h0 + a_c * 8);
                }
                #pragma unroll
                for (int p = 0; p < 4; p++) {
                    const int row = a_row + p * 64;
                    cp16(Bn + row * ROWB + a_c * 16,
                         g_uw_hi + (size_t)(kc * KC + row) * Hsz + h0 + a_c * 8);
                    cp16(Bn + B_BUF + row * ROWB + a_c * 16,
                         g_uw_lo + (size_t)(kc * KC + row) * Hsz + h0 + a_c * 8);
                }
                CP_COMMIT();
                CP_WAIT(1);
            } else {
                CP_WAIT(0);
            }
            __syncthreads();   // chunk `cur` data visible to all warps

            // ---- MMA block on current buffer ----
            const uint32_t a_hi = sbase + SM_A + cur * (2 * A_BUF);
            const uint32_t a_lo = a_hi + A_BUF;
            const uint32_t b_hi = sbase + SM_B + cur * (2 * B_BUF);
            const uint32_t b_lo = b_hi + B_BUF;

            #pragma unroll
            for (int ks = 0; ks < 2; ks++) {
                uint32_t ah[4], al[4];
                ldsm_x4(ah, a_hi + arow * ROWB + ks * 32 + aco);
                ldsm_x4(al, a_lo + arow * ROWB + ks * 32 + aco);
                const uint32_t bh0 = b_hi + bn * ROWB + ks * 32 + bco;
                const uint32_t bl0 = b_lo + bn * ROWB + ks * 32 + bco;
                #pragma unroll
                for (int nt2 = 0; nt2 < NT / 2; nt2++) {
                    uint32_t bh[4], bl[4];
                    ldsm_x4(bh, bh0 + nt2 * 16 * ROWB);
                    ldsm_x4(bl, bl0 + nt2 * 16 * ROWB);
                    mma_bf16(acc[2 * nt2],     ah, bh);
                    mma_bf16(acc[2 * nt2],     ah, bl);
                    mma_bf16(acc[2 * nt2],     al, bh);
                    mma_bf16(acc[2 * nt2 + 1], ah, bh + 2);
                    mma_bf16(acc[2 * nt2 + 1], ah, bl + 2);
                    mma_bf16(acc[2 * nt2 + 1], al, bh + 2);
                }
            }
            __syncthreads();   // all warps done reading `cur` before it is refilled
        }

        // ---- epilogue: tanh + va-weighted reduction over this kc's 256 cols ----
        float p0 = 0.f, p1 = 0.f;
        #pragma unroll
        for (int nt = 0; nt < NT; nt++) {
            const int col = nt * 8 + (lane & 3) * 2;
            const int k = kc * KC + col;
            const float c0 = s_c[k], c1 = s_c[k + 1];
            const float v0 = s_va[k], v1 = s_va[k + 1];
            p0 += v0 * tanhf(acc[nt][0] + c0);
            p0 += v1 * tanhf(acc[nt][1] + c1);
            p1 += v0 * tanhf(acc[nt][2] + c0);
            p1 += v1 * tanhf(acc[nt][3] + c1);
        }
        p0 += __shfl_xor_sync(0xffffffffu, p0, 1);
        p0 += __shfl_xor_sync(0xffffffffu, p0, 2);
        p1 += __shfl_xor_sync(0xffffffffu, p1, 1);
        p1 += __shfl_xor_sync(0xffffffffu, p1, 2);
        sc0 += p0;
        sc1 += p1;
    }

    // ---- write scores ----
    if ((lane & 3) == 0) {
        const int r = lane >> 2;
        int l = l0 + w * 16 + r;
        float s = sc0 + va_b[0];
        if (mask[b * Lsz + l]) s = -INFINITY;
        g_scores[b * Lsz + l] = s;
        l += 8;
        s = sc1 + va_b[0];
        if (mask[b * Lsz + l]) s = -INFINITY;
        g_scores[b * Lsz + l] = s;
    }
}

// ---------------------------------------------------------------------------
// Kernel C: softmax over L per batch
// ---------------------------------------------------------------------------
__global__ __launch_bounds__(256) void softmax_kernel()
{
    __shared__ float red[256];
    const int b = blockIdx.x;
    const int tid = threadIdx.x;

    float mx = -INFINITY;
    for (int l = tid; l < Lsz; l += 256) mx = fmaxf(mx, g_scores[b * Lsz + l]);
    red[tid] = mx;
    __syncthreads();
    for (int s = 128; s; s >>= 1) {
        if (tid < s) red[tid] = fmaxf(red[tid], red[tid + s]);
        __syncthreads();
    }
    mx = red[0];
    __syncthreads();

    float sum = 0.f;
    for (int l = tid; l < Lsz; l += 256) {
        const float e = expf(g_scores[b * Lsz + l] - mx);
        g_weights[b * Lsz + l] = e;
        sum += e;
    }
    red[tid] = sum;
    __syncthreads();
    for (int s = 128; s; s >>= 1) {
        if (tid < s) red[tid] += red[tid + s];
        __syncthreads();
    }
    const float inv = 1.f / red[0];
    for (int l = tid; l < Lsz; l += 256) g_weights[b * Lsz + l] *= inv;
}

// ---------------------------------------------------------------------------
// Kernel D: partial contexts
// ---------------------------------------------------------------------------
__global__ __launch_bounds__(256) void context_kernel(const float* __restrict__ keys)
{
    __shared__ float wsh[256];
    const int s = blockIdx.x;
    const int b = blockIdx.y;
    const int t = threadIdx.x;

    wsh[t] = g_weights[b * Lsz + s * 256 + t];
    __syncthreads();

    float4 acc = make_float4(0.f, 0.f, 0.f, 0.f);
    const float* kb = keys + ((size_t)b * Lsz + s * 256) * Hsz;
    #pragma unroll 4
    for (int l = 0; l < 256; l++) {
        const float w = wsh[l];
        float4 kv = *(const float4*)(kb + (size_t)l * Hsz + t * 4);
        acc.x += w * kv.x;
        acc.y += w * kv.y;
        acc.z += w * kv.z;
        acc.w += w * kv.w;
    }
    *(float4*)&g_part[s][b * Hsz + t * 4] = acc;
}

// ---------------------------------------------------------------------------
// Kernel E: reduce partials
// ---------------------------------------------------------------------------
__global__ __launch_bounds__(256) void reduce_kernel(float* __restrict__ out)
{
    const int i = blockIdx.x * 256 + threadIdx.x;
    float s = 0.f;
    #pragma unroll
    for (int p = 0; p < 8; p++) s += g_part[p][i];
    out[i] = s;
}

// ---------------------------------------------------------------------------
extern "C" void kernel_launch(void* const* d_in, const int* in_sizes, int n_in,
                              void* d_out, int out_size)
{
    const float* query = (const float*)d_in[0];
    const float* keys  = (const float*)d_in[1];
    const unsigned char* mask = (const unsigned char*)d_in[2];
    const float* wa_w = (const float*)d_in[3];
    const float* wa_b = (const float*)d_in[4];
    const float* ua_w = (const float*)d_in[5];
    const float* ua_b = (const float*)d_in[6];
    const float* va_w = (const float*)d_in[7];
    const float* va_b = (const float*)d_in[8];
    float* out = (float*)d_out;

    cudaFuncSetAttribute(scores_mma_kernel,
                         cudaFuncAttributeMaxDynamicSharedMemorySize, SM_TOTAL);

    presplit_uw_kernel<<<(Hsz * Hsz / 4) / 256, 256>>>(ua_w);
    presplit_keys_kernel<<<(int)(((size_t)Bsz * Lsz * Hsz / 4) / 256), 256>>>(keys);
    wq_kernel<<<Bsz, 256>>>(query, wa_w, wa_b);
    scores_mma_kernel<<<dim3(Lsz / TM, Bsz), 256, SM_TOTAL>>>(
        ua_b, va_w, va_b, mask);
    softmax_kernel<<<Bsz, 256>>>();
    context_kernel<<<dim3(8, Bsz), 256>>>(keys);
    reduce_kernel<<<(Bsz * Hsz) / 256, 256>>>(out);
}

// round 13
// speedup vs baseline: 1.0481x; 1.0481x over previous
#include <cuda_runtime.h>
#include <cuda_bf16.h>
#include <math.h>
#include <stdint.h>

// Problem constants
constexpr int Bsz = 32;
constexpr int Lsz = 2048;
constexpr int Hsz = 1024;

// Scratch
__device__ float g_wq[Bsz * Hsz];
__device__ float g_scores[Bsz * Lsz];
__device__ float g_weights[Bsz * Lsz];
__device__ float g_part[8][Bsz * Hsz];
__device__ __align__(16) __nv_bfloat16 g_uw_hi[Hsz * Hsz];        // ua_w hi
__device__ __align__(16) __nv_bfloat16 g_uw_lo[Hsz * Hsz];        // ua_w lo
__device__ __align__(16) __nv_bfloat16 g_k_hi[Bsz * Lsz * Hsz];   // keys hi (128MB)
__device__ __align__(16) __nv_bfloat16 g_k_lo[Bsz * Lsz * Hsz];   // keys lo (128MB)

// ---------------------------------------------------------------------------
// mma.sync / ldmatrix / cp.async helpers
// ---------------------------------------------------------------------------
__device__ __forceinline__ uint32_t smem_to_u32(const void* p) {
    uint32_t a;
    asm("{ .reg .u64 t; cvta.to.shared.u64 t, %1; cvt.u32.u64 %0, t; }" : "=r"(a) : "l"(p));
    return a;
}
__device__ __forceinline__ void ldsm_x4(uint32_t* r, uint32_t addr) {
    asm volatile("ldmatrix.sync.aligned.m8n8.x4.shared.b16 {%0,%1,%2,%3}, [%4];"
        : "=r"(r[0]), "=r"(r[1]), "=r"(r[2]), "=r"(r[3]) : "r"(addr));
}
__device__ __forceinline__ void mma_bf16(float* c, const uint32_t* a, const uint32_t* b) {
    asm volatile("mma.sync.aligned.m16n8k16.row.col.f32.bf16.bf16.f32 "
        "{%0,%1,%2,%3}, {%4,%5,%6,%7}, {%8,%9}, {%0,%1,%2,%3};"
        : "+f"(c[0]), "+f"(c[1]), "+f"(c[2]), "+f"(c[3])
        : "r"(a[0]), "r"(a[1]), "r"(a[2]), "r"(a[3]), "r"(b[0]), "r"(b[1]));
}
__device__ __forceinline__ void cp16(uint32_t dst, const void* src) {
    asm volatile("cp.async.cg.shared.global [%0], [%1], 16;" :: "r"(dst), "l"(src));
}
#define CP_COMMIT() asm volatile("cp.async.commit_group;" ::: "memory")
#define CP_WAIT(n)  asm volatile("cp.async.wait_group %0;" :: "n"(n) : "memory")

// ---------------------------------------------------------------------------
// Split helpers
// ---------------------------------------------------------------------------
__device__ __forceinline__ void split4(float4 v, uint2& hu, uint2& lu) {
    __nv_bfloat16 h0 = __float2bfloat16_rn(v.x);
    __nv_bfloat16 h1 = __float2bfloat16_rn(v.y);
    __nv_bfloat16 h2 = __float2bfloat16_rn(v.z);
    __nv_bfloat16 h3 = __float2bfloat16_rn(v.w);
    __nv_bfloat16 l0 = __float2bfloat16_rn(v.x - __bfloat162float(h0));
    __nv_bfloat16 l1 = __float2bfloat16_rn(v.y - __bfloat162float(h1));
    __nv_bfloat16 l2 = __float2bfloat16_rn(v.z - __bfloat162float(h2));
    __nv_bfloat16 l3 = __float2bfloat16_rn(v.w - __bfloat162float(h3));
    __nv_bfloat162 ha = __halves2bfloat162(h0, h1), hb = __halves2bfloat162(h2, h3);
    __nv_bfloat162 la = __halves2bfloat162(l0, l1), lb = __halves2bfloat162(l2, l3);
    hu = make_uint2(*reinterpret_cast<uint32_t*>(&ha), *reinterpret_cast<uint32_t*>(&hb));
    lu = make_uint2(*reinterpret_cast<uint32_t*>(&la), *reinterpret_cast<uint32_t*>(&lb));
}

__global__ __launch_bounds__(256) void presplit_uw_kernel(const float* __restrict__ ua_w)
{
    const int i4 = blockIdx.x * 256 + threadIdx.x;
    uint2 hu, lu;
    split4(((const float4*)ua_w)[i4], hu, lu);
    ((uint2*)g_uw_hi)[i4] = hu;
    ((uint2*)g_uw_lo)[i4] = lu;
}

__global__ __launch_bounds__(256) void presplit_keys_kernel(const float* __restrict__ keys)
{
    const size_t i4 = (size_t)blockIdx.x * 256 + threadIdx.x;
    uint2 hu, lu;
    split4(((const float4*)keys)[i4], hu, lu);
    ((uint2*)g_k_hi)[i4] = hu;
    ((uint2*)g_k_lo)[i4] = lu;
}

// ---------------------------------------------------------------------------
// Kernel A: wq[b,k] = query[b,:]·wa_w[k,:] + wa_b[k]
// ---------------------------------------------------------------------------
__global__ __launch_bounds__(256) void wq_kernel(
    const float* __restrict__ query, const float* __restrict__ wa_w,
    const float* __restrict__ wa_b)
{
    __shared__ __align__(16) float qs[Hsz];
    const int b = blockIdx.x;
    for (int i = threadIdx.x; i < Hsz / 4; i += blockDim.x)
        ((float4*)qs)[i] = ((const float4*)(query + (size_t)b * Hsz))[i];
    __syncthreads();

    const int warp = threadIdx.x >> 5;
    const int lane = threadIdx.x & 31;
    for (int k = warp; k < Hsz; k += 8) {
        const float4* wrow = (const float4*)(wa_w + (size_t)k * Hsz);
        float sum = 0.f;
        #pragma unroll
        for (int i = 0; i < 8; i++) {
            float4 wv = wrow[lane + 32 * i];
            float4 qv = ((const float4*)qs)[lane + 32 * i];
            sum += wv.x * qv.x + wv.y * qv.y + wv.z * qv.z + wv.w * qv.w;
        }
        #pragma unroll
        for (int off = 16; off; off >>= 1)
            sum += __shfl_down_sync(0xffffffffu, sum, off);
        if (lane == 0) g_wq[b * Hsz + k] = sum + wa_b[k];
    }
}

// ---------------------------------------------------------------------------
// Kernel B: fused scores via bf16x3 mma.sync, cp.async staging.
// KC=128 (acc = 64 regs) + launch_bounds(256,2) -> 2 CTAs/SM, no spills.
// ---------------------------------------------------------------------------
constexpr int TM = 128;
constexpr int KC = 128;
constexpr int NT = KC / 8;      // 16 n8-tiles
constexpr int HC = 32;
constexpr int NHC = Hsz / HC;   // 32
constexpr int ROWB = 80;        // 64B data + 16B pad -> conflict-free ldsm

constexpr int SM_C   = 0;                     // wq+ua_b: 4KB
constexpr int SM_VA  = 4096;                  // va_w:    4KB
constexpr int SM_A   = 8192;                  // A: [buf][hi/lo][128*80]
constexpr int A_BUF  = TM * ROWB;             // 10240
constexpr int SM_B   = SM_A + 4 * A_BUF;      // 49152; B: [buf][hi/lo][128*80]
constexpr int B_BUF  = KC * ROWB;             // 10240
constexpr int SM_TOTAL = SM_B + 4 * B_BUF;    // 90112  (2 CTAs fit in 228KB)

__global__ __launch_bounds__(256, 2) void scores_mma_kernel(
    const float* __restrict__ ua_b,
    const float* __restrict__ va_w,
    const float* __restrict__ va_b,
    const unsigned char* __restrict__ mask)
{
    extern __shared__ __align__(128) char smem[];
    const uint32_t sbase = smem_to_u32(smem);
    const int tid  = threadIdx.x;
    const int lane = tid & 31;
    const int w    = tid >> 5;
    const int b    = blockIdx.y;
    const int l0   = blockIdx.x * TM;

    float* s_c  = (float*)(smem + SM_C);
    float* s_va = (float*)(smem + SM_VA);
    for (int i = tid; i < Hsz; i += 256) {
        s_c[i]  = g_wq[b * Hsz + i] + ua_b[i];
        s_va[i] = va_w[i];
    }

    const __nv_bfloat16* kHi = g_k_hi + ((size_t)b * Lsz + l0) * Hsz;
    const __nv_bfloat16* kLo = g_k_lo + ((size_t)b * Lsz + l0) * Hsz;

    float sc0 = 0.f, sc1 = 0.f;

    // ldmatrix per-lane addressing
    const int arow = w * 16 + (lane & 15);             // A tile row
    const int aco  = (lane >> 4) << 4;                 // A k-half byte offset
    const int bn   = (lane & 7) | ((lane >> 4) << 3);  // B row 0..15 (two n8 tiles)
    const int bco  = ((lane >> 3) & 1) << 4;           // B k-half byte offset

    // cp.async staging indices
    const int a_row = tid >> 2;     // 0..63, +p*64
    const int a_c   = tid & 3;

    #pragma unroll 1
    for (int kc = 0; kc < 8; kc++) {
        float acc[NT][4];
        #pragma unroll
        for (int nt = 0; nt < NT; nt++)
            #pragma unroll
            for (int j = 0; j < 4; j++) acc[nt][j] = 0.f;

        // ---- issue chunk 0 into buffer 0 ----
        {
            const uint32_t A0 = sbase + SM_A;
            const uint32_t B0 = sbase + SM_B;
            #pragma unroll
            for (int p = 0; p < 2; p++) {   // A hi/lo: 128 rows
                const int row = a_row + p * 64;
                cp16(A0 + row * ROWB + a_c * 16,
                     kHi + (size_t)row * Hsz + a_c * 8);
                cp16(A0 + A_BUF + row * ROWB + a_c * 16,
                     kLo + (size_t)row * Hsz + a_c * 8);
            }
            #pragma unroll
            for (int p = 0; p < 2; p++) {   // B hi/lo: 128 rows
                const int row = a_row + p * 64;
                cp16(B0 + row * ROWB + a_c * 16,
                     g_uw_hi + (size_t)(kc * KC + row) * Hsz + a_c * 8);
                cp16(B0 + B_BUF + row * ROWB + a_c * 16,
                     g_uw_lo + (size_t)(kc * KC + row) * Hsz + a_c * 8);
            }
            CP_COMMIT();
        }

        #pragma unroll 1
        for (int hc = 0; hc < NHC; hc++) {
            const int cur = hc & 1, nxt = cur ^ 1;
            const bool pf = (hc + 1 < NHC);

            // ---- issue next chunk into other buffer ----
            if (pf) {
                const int h0 = (hc + 1) * HC;
                const uint32_t An = sbase + SM_A + nxt * (2 * A_BUF);
                const uint32_t Bn = sbase + SM_B + nxt * (2 * B_BUF);
                #pragma unroll
                for (int p = 0; p < 2; p++) {
                    const int row = a_row + p * 64;
                    cp16(An + row * ROWB + a_c * 16,
                         kHi + (size_t)row * Hsz + h0 + a_c * 8);
                    cp16(An + A_BUF + row * ROWB + a_c * 16,
                         kLo + (size_t)row * Hsz + h0 + a_c * 8);
                }
                #pragma unroll
                for (int p = 0; p < 2; p++) {
                    const int row = a_row + p * 64;
                    cp16(Bn + row * ROWB + a_c * 16,
                         g_uw_hi + (size_t)(kc * KC + row) * Hsz + h0 + a_c * 8);
                    cp16(Bn + B_BUF + row * ROWB + a_c * 16,
                         g_uw_lo + (size_t)(kc * KC + row) * Hsz + h0 + a_c * 8);
                }
                CP_COMMIT();
                CP_WAIT(1);
            } else {
                CP_WAIT(0);
            }
            __syncthreads();   // chunk `cur` visible to all warps

            // ---- MMA block on current buffer ----
            const uint32_t a_hi = sbase + SM_A + cur * (2 * A_BUF);
            const uint32_t a_lo = a_hi + A_BUF;
            const uint32_t b_hi = sbase + SM_B + cur * (2 * B_BUF);
            const uint32_t b_lo = b_hi + B_BUF;

            #pragma unroll
            for (int ks = 0; ks < 2; ks++) {
                uint32_t ah[4], al[4];
                ldsm_x4(ah, a_hi + arow * ROWB + ks * 32 + aco);
                ldsm_x4(al, a_lo + arow * ROWB + ks * 32 + aco);
                const uint32_t bh0 = b_hi + bn * ROWB + ks * 32 + bco;
                const uint32_t bl0 = b_lo + bn * ROWB + ks * 32 + bco;
                #pragma unroll
                for (int nt2 = 0; nt2 < NT / 2; nt2++) {
                    uint32_t bh[4], bl[4];
                    ldsm_x4(bh, bh0 + nt2 * 16 * ROWB);
                    ldsm_x4(bl, bl0 + nt2 * 16 * ROWB);
                    mma_bf16(acc[2 * nt2],     ah, bh);
                    mma_bf16(acc[2 * nt2],     ah, bl);
                    mma_bf16(acc[2 * nt2],     al, bh);
                    mma_bf16(acc[2 * nt2 + 1], ah, bh + 2);
                    mma_bf16(acc[2 * nt2 + 1], ah, bl + 2);
                    mma_bf16(acc[2 * nt2 + 1], al, bh + 2);
                }
            }
            __syncthreads();   // all warps done reading `cur` before refill
        }

        // ---- epilogue: tanh + va-weighted reduction over this kc's 128 cols ----
        float p0 = 0.f, p1 = 0.f;
        #pragma unroll
        for (int nt = 0; nt < NT; nt++) {
            const int col = nt * 8 + (lane & 3) * 2;
            const int k = kc * KC + col;
            const float c0 = s_c[k], c1 = s_c[k + 1];
            const float v0 = s_va[k], v1 = s_va[k + 1];
            p0 += v0 * tanhf(acc[nt][0] + c0);
            p0 += v1 * tanhf(acc[nt][1] + c1);
            p1 += v0 * tanhf(acc[nt][2] + c0);
            p1 += v1 * tanhf(acc[nt][3] + c1);
        }
        p0 += __shfl_xor_sync(0xffffffffu, p0, 1);
        p0 += __shfl_xor_sync(0xffffffffu, p0, 2);
        p1 += __shfl_xor_sync(0xffffffffu, p1, 1);
        p1 += __shfl_xor_sync(0xffffffffu, p1, 2);
        sc0 += p0;
        sc1 += p1;
    }

    // ---- write scores ----
    if ((lane & 3) == 0) {
        const int r = lane >> 2;
        int l = l0 + w * 16 + r;
        float s = sc0 + va_b[0];
        if (mask[b * Lsz + l]) s = -INFINITY;
        g_scores[b * Lsz + l] = s;
        l += 8;
        s = sc1 + va_b[0];
        if (mask[b * Lsz + l]) s = -INFINITY;
        g_scores[b * Lsz + l] = s;
    }
}

// ---------------------------------------------------------------------------
// Kernel C: softmax over L per batch
// ---------------------------------------------------------------------------
__global__ __launch_bounds__(256) void softmax_kernel()
{
    __shared__ float red[256];
    const int b = blockIdx.x;
    const int tid = threadIdx.x;

    float mx = -INFINITY;
    for (int l = tid; l < Lsz; l += 256) mx = fmaxf(mx, g_scores[b * Lsz + l]);
    red[tid] = mx;
    __syncthreads();
    for (int s = 128; s; s >>= 1) {
        if (tid < s) red[tid] = fmaxf(red[tid], red[tid + s]);
        __syncthreads();
    }
    mx = red[0];
    __syncthreads();

    float sum = 0.f;
    for (int l = tid; l < Lsz; l += 256) {
        const float e = expf(g_scores[b * Lsz + l] - mx);
        g_weights[b * Lsz + l] = e;
        sum += e;
    }
    red[tid] = sum;
    __syncthreads();
    for (int s = 128; s; s >>= 1) {
        if (tid < s) red[tid] += red[tid + s];
        __syncthreads();
    }
    const float inv = 1.f / red[0];
    for (int l = tid; l < Lsz; l += 256) g_weights[b * Lsz + l] *= inv;
}

// ---------------------------------------------------------------------------
// Kernel D: partial contexts
// ---------------------------------------------------------------------------
__global__ __launch_bounds__(256) void context_kernel(const float* __restrict__ keys)
{
    __shared__ float wsh[256];
    const int s = blockIdx.x;
    const int b = blockIdx.y;
    const int t = threadIdx.x;

    wsh[t] = g_weights[b * Lsz + s * 256 + t];
    __syncthreads();

    float4 acc = make_float4(0.f, 0.f, 0.f, 0.f);
    const float* kb = keys + ((size_t)b * Lsz + s * 256) * Hsz;
    #pragma unroll 4
    for (int l = 0; l < 256; l++) {
        const float w = wsh[l];
        float4 kv = *(const float4*)(kb + (size_t)l * Hsz + t * 4);
        acc.x += w * kv.x;
        acc.y += w * kv.y;
        acc.z += w * kv.z;
        acc.w += w * kv.w;
    }
    *(float4*)&g_part[s][b * Hsz + t * 4] = acc;
}

// ---------------------------------------------------------------------------
// Kernel E: reduce partials
// ---------------------------------------------------------------------------
__global__ __launch_bounds__(256) void reduce_kernel(float* __restrict__ out)
{
    const int i = blockIdx.x * 256 + threadIdx.x;
    float s = 0.f;
    #pragma unroll
    for (int p = 0; p < 8; p++) s += g_part[p][i];
    out[i] = s;
}

// ---------------------------------------------------------------------------
extern "C" void kernel_launch(void* const* d_in, const int* in_sizes, int n_in,
                              void* d_out, int out_size)
{
    const float* query = (const float*)d_in[0];
    const float* keys  = (const float*)d_in[1];
    const unsigned char* mask = (const unsigned char*)d_in[2];
    const float* wa_w = (const float*)d_in[3];
    const float* wa_b = (const float*)d_in[4];
    const float* ua_w = (const float*)d_in[5];
    const float* ua_b = (const float*)d_in[6];
    const float* va_w = (const float*)d_in[7];
    const float* va_b = (const float*)d_in[8];
    float* out = (float*)d_out;

    cudaFuncSetAttribute(scores_mma_kernel,
                         cudaFuncAttributeMaxDynamicSharedMemorySize, SM_TOTAL);

    presplit_uw_kernel<<<(Hsz * Hsz / 4) / 256, 256>>>(ua_w);
    presplit_keys_kernel<<<(int)(((size_t)Bsz * Lsz * Hsz / 4) / 256), 256>>>(keys);
    wq_kernel<<<Bsz, 256>>>(query, wa_w, wa_b);
    scores_mma_kernel<<<dim3(Lsz / TM, Bsz), 256, SM_TOTAL>>>(
        ua_b, va_w, va_b, mask);
    softmax_kernel<<<Bsz, 256>>>();
    context_kernel<<<dim3(8, Bsz), 256>>>(keys);
    reduce_kernel<<<(Bsz * Hsz) / 256, 256>>>(out);
}

// round 14
// speedup vs baseline: 1.0720x; 1.0227x over previous
#include <cuda_runtime.h>
#include <cuda_bf16.h>
#include <math.h>
#include <stdint.h>

// Problem constants
constexpr int Bsz = 32;
constexpr int Lsz = 2048;
constexpr int Hsz = 1024;

// Scratch
__device__ float g_wq[Bsz * Hsz];
__device__ float g_scores[Bsz * Lsz];
__device__ float g_weights[Bsz * Lsz];
__device__ float g_part[8][Bsz * Hsz];
__device__ __align__(16) __nv_bfloat16 g_uw_hi[Hsz * Hsz];        // ua_w hi
__device__ __align__(16) __nv_bfloat16 g_uw_lo[Hsz * Hsz];        // ua_w lo
__device__ __align__(16) __nv_bfloat16 g_k_hi[Bsz * Lsz * Hsz];   // keys hi (128MB)
__device__ __align__(16) __nv_bfloat16 g_k_lo[Bsz * Lsz * Hsz];   // keys lo (128MB)

// ---------------------------------------------------------------------------
// mma.sync / ldmatrix / cp.async helpers
// ---------------------------------------------------------------------------
__device__ __forceinline__ uint32_t smem_to_u32(const void* p) {
    uint32_t a;
    asm("{ .reg .u64 t; cvta.to.shared.u64 t, %1; cvt.u32.u64 %0, t; }" : "=r"(a) : "l"(p));
    return a;
}
__device__ __forceinline__ void ldsm_x4(uint32_t* r, uint32_t addr) {
    asm volatile("ldmatrix.sync.aligned.m8n8.x4.shared.b16 {%0,%1,%2,%3}, [%4];"
        : "=r"(r[0]), "=r"(r[1]), "=r"(r[2]), "=r"(r[3]) : "r"(addr));
}
__device__ __forceinline__ void mma_bf16(float* c, const uint32_t* a, const uint32_t* b) {
    asm volatile("mma.sync.aligned.m16n8k16.row.col.f32.bf16.bf16.f32 "
        "{%0,%1,%2,%3}, {%4,%5,%6,%7}, {%8,%9}, {%0,%1,%2,%3};"
        : "+f"(c[0]), "+f"(c[1]), "+f"(c[2]), "+f"(c[3])
        : "r"(a[0]), "r"(a[1]), "r"(a[2]), "r"(a[3]), "r"(b[0]), "r"(b[1]));
}
__device__ __forceinline__ void cp16(uint32_t dst, const void* src) {
    asm volatile("cp.async.cg.shared.global [%0], [%1], 16;" :: "r"(dst), "l"(src));
}
#define CP_COMMIT() asm volatile("cp.async.commit_group;" ::: "memory")
#define CP_WAIT(n)  asm volatile("cp.async.wait_group %0;" :: "n"(n) : "memory")

// ---------------------------------------------------------------------------
// Split helpers
// ---------------------------------------------------------------------------
__device__ __forceinline__ void split4(float4 v, uint2& hu, uint2& lu) {
    __nv_bfloat16 h0 = __float2bfloat16_rn(v.x);
    __nv_bfloat16 h1 = __float2bfloat16_rn(v.y);
    __nv_bfloat16 h2 = __float2bfloat16_rn(v.z);
    __nv_bfloat16 h3 = __float2bfloat16_rn(v.w);
    __nv_bfloat16 l0 = __float2bfloat16_rn(v.x - __bfloat162float(h0));
    __nv_bfloat16 l1 = __float2bfloat16_rn(v.y - __bfloat162float(h1));
    __nv_bfloat16 l2 = __float2bfloat16_rn(v.z - __bfloat162float(h2));
    __nv_bfloat16 l3 = __float2bfloat16_rn(v.w - __bfloat162float(h3));
    __nv_bfloat162 ha = __halves2bfloat162(h0, h1), hb = __halves2bfloat162(h2, h3);
    __nv_bfloat162 la = __halves2bfloat162(l0, l1), lb = __halves2bfloat162(l2, l3);
    hu = make_uint2(*reinterpret_cast<uint32_t*>(&ha), *reinterpret_cast<uint32_t*>(&hb));
    lu = make_uint2(*reinterpret_cast<uint32_t*>(&la), *reinterpret_cast<uint32_t*>(&lb));
}

__global__ __launch_bounds__(256) void presplit_uw_kernel(const float* __restrict__ ua_w)
{
    const int i4 = blockIdx.x * 256 + threadIdx.x;
    uint2 hu, lu;
    split4(((const float4*)ua_w)[i4], hu, lu);
    ((uint2*)g_uw_hi)[i4] = hu;
    ((uint2*)g_uw_lo)[i4] = lu;
}

__global__ __launch_bounds__(256) void presplit_keys_kernel(const float* __restrict__ keys)
{
    const size_t i4 = (size_t)blockIdx.x * 256 + threadIdx.x;
    uint2 hu, lu;
    split4(((const float4*)keys)[i4], hu, lu);
    ((uint2*)g_k_hi)[i4] = hu;
    ((uint2*)g_k_lo)[i4] = lu;
}

// ---------------------------------------------------------------------------
// Kernel A: wq[b,k] = query[b,:]·wa_w[k,:] + wa_b[k]
// ---------------------------------------------------------------------------
__global__ __launch_bounds__(256) void wq_kernel(
    const float* __restrict__ query, const float* __restrict__ wa_w,
    const float* __restrict__ wa_b)
{
    __shared__ __align__(16) float qs[Hsz];
    const int b = blockIdx.x;
    for (int i = threadIdx.x; i < Hsz / 4; i += blockDim.x)
        ((float4*)qs)[i] = ((const float4*)(query + (size_t)b * Hsz))[i];
    __syncthreads();

    const int warp = threadIdx.x >> 5;
    const int lane = threadIdx.x & 31;
    for (int k = warp; k < Hsz; k += 8) {
        const float4* wrow = (const float4*)(wa_w + (size_t)k * Hsz);
        float sum = 0.f;
        #pragma unroll
        for (int i = 0; i < 8; i++) {
            float4 wv = wrow[lane + 32 * i];
            float4 qv = ((const float4*)qs)[lane + 32 * i];
            sum += wv.x * qv.x + wv.y * qv.y + wv.z * qv.z + wv.w * qv.w;
        }
        #pragma unroll
        for (int off = 16; off; off >>= 1)
            sum += __shfl_down_sync(0xffffffffu, sum, off);
        if (lane == 0) g_wq[b * Hsz + k] = sum + wa_b[k];
    }
}

// ---------------------------------------------------------------------------
// Kernel B: fused scores via bf16x3 mma.sync, cp.async staging.
// 2D warp tiling: 4 M-warps x 2 N-warps; warp tile M32 x N64 (acc = 64 regs).
// Halves duplicated B ldsm traffic -> tensor-pipe bound.
// ---------------------------------------------------------------------------
constexpr int TM = 128;
constexpr int KC = 128;
constexpr int HC = 32;
constexpr int NHC = Hsz / HC;   // 32
constexpr int ROWB = 80;        // 64B data + 16B pad -> conflict-free ldsm

constexpr int SM_C   = 0;                     // wq+ua_b: 4KB
constexpr int SM_VA  = 4096;                  // va_w:    4KB
constexpr int SM_A   = 8192;                  // A: [buf][hi/lo][128*80]
constexpr int A_BUF  = TM * ROWB;             // 10240
constexpr int SM_B   = SM_A + 4 * A_BUF;      // 49152; B: [buf][hi/lo][128*80]
constexpr int B_BUF  = KC * ROWB;             // 10240
constexpr int SM_RED = SM_B + 4 * B_BUF;      // 90112; cross-warp: 2*128 f32
constexpr int SM_TOTAL = SM_RED + 1024;       // 91136  (2 CTAs fit in 228KB)

__global__ __launch_bounds__(256, 2) void scores_mma_kernel(
    const float* __restrict__ ua_b,
    const float* __restrict__ va_w,
    const float* __restrict__ va_b,
    const unsigned char* __restrict__ mask)
{
    extern __shared__ __align__(128) char smem[];
    const uint32_t sbase = smem_to_u32(smem);
    const int tid  = threadIdx.x;
    const int lane = tid & 31;
    const int w    = tid >> 5;
    const int mw   = w & 3;          // M-warp group: rows [mw*32, mw*32+32)
    const int nw   = w >> 2;         // N-warp group: cols [nw*64, nw*64+64)
    const int b    = blockIdx.y;
    const int l0   = blockIdx.x * TM;

    float* s_c   = (float*)(smem + SM_C);
    float* s_va  = (float*)(smem + SM_VA);
    float* s_red = (float*)(smem + SM_RED);
    for (int i = tid; i < Hsz; i += 256) {
        s_c[i]  = g_wq[b * Hsz + i] + ua_b[i];
        s_va[i] = va_w[i];
    }

    const __nv_bfloat16* kHi = g_k_hi + ((size_t)b * Lsz + l0) * Hsz;
    const __nv_bfloat16* kLo = g_k_lo + ((size_t)b * Lsz + l0) * Hsz;

    float sc[4] = {0.f, 0.f, 0.f, 0.f};  // [mt*2 + half] row-group partials

    // ldmatrix per-lane addressing
    const int arow0 = mw * 32 + (lane & 15);           // A row, m-tile 0 (+16 for mt1)
    const int aco   = (lane >> 4) << 4;                // A k-half byte offset
    const int bn    = (lane & 7) | ((lane >> 4) << 3); // B row 0..15 (two n8 tiles)
    const int bco   = ((lane >> 3) & 1) << 4;          // B k-half byte offset
    const int brow0 = nw * 64 + bn;                    // B row base for this N-warp

    // cp.async staging indices
    const int a_row = tid >> 2;     // 0..63, +p*64
    const int a_c   = tid & 3;

    #pragma unroll 1
    for (int kc = 0; kc < 8; kc++) {
        float acc[16][4];   // [mt*8 + nt][4]
        #pragma unroll
        for (int nt = 0; nt < 16; nt++)
            #pragma unroll
            for (int j = 0; j < 4; j++) acc[nt][j] = 0.f;

        // ---- issue chunk 0 into buffer 0 ----
        {
            const uint32_t A0 = sbase + SM_A;
            const uint32_t B0 = sbase + SM_B;
            #pragma unroll
            for (int p = 0; p < 2; p++) {   // A hi/lo: 128 rows
                const int row = a_row + p * 64;
                cp16(A0 + row * ROWB + a_c * 16,
                     kHi + (size_t)row * Hsz + a_c * 8);
                cp16(A0 + A_BUF + row * ROWB + a_c * 16,
                     kLo + (size_t)row * Hsz + a_c * 8);
            }
            #pragma unroll
            for (int p = 0; p < 2; p++) {   // B hi/lo: 128 rows
                const int row = a_row + p * 64;
                cp16(B0 + row * ROWB + a_c * 16,
                     g_uw_hi + (size_t)(kc * KC + row) * Hsz + a_c * 8);
                cp16(B0 + B_BUF + row * ROWB + a_c * 16,
                     g_uw_lo + (size_t)(kc * KC + row) * Hsz + a_c * 8);
            }
            CP_COMMIT();
        }

        #pragma unroll 1
        for (int hc = 0; hc < NHC; hc++) {
            const int cur = hc & 1, nxt = cur ^ 1;
            const bool pf = (hc + 1 < NHC);

            // ---- issue next chunk into other buffer ----
            if (pf) {
                const int h0 = (hc + 1) * HC;
                const uint32_t An = sbase + SM_A + nxt * (2 * A_BUF);
                const uint32_t Bn = sbase + SM_B + nxt * (2 * B_BUF);
                #pragma unroll
                for (int p = 0; p < 2; p++) {
                    const int row = a_row + p * 64;
                    cp16(An + row * ROWB + a_c * 16,
                         kHi + (size_t)row * Hsz + h0 + a_c * 8);
                    cp16(An + A_BUF + row * ROWB + a_c * 16,
                         kLo + (size_t)row * Hsz + h0 + a_c * 8);
                }
                #pragma unroll
                for (int p = 0; p < 2; p++) {
                    const int row = a_row + p * 64;
                    cp16(Bn + row * ROWB + a_c * 16,
                         g_uw_hi + (size_t)(kc * KC + row) * Hsz + h0 + a_c * 8);
                    cp16(Bn + B_BUF + row * ROWB + a_c * 16,
                         g_uw_lo + (size_t)(kc * KC + row) * Hsz + h0 + a_c * 8);
                }
                CP_COMMIT();
                CP_WAIT(1);
            } else {
                CP_WAIT(0);
            }
            __syncthreads();   // chunk `cur` visible to all warps

            // ---- MMA block on current buffer (warp tile M32 x N64) ----
            const uint32_t a_hi = sbase + SM_A + cur * (2 * A_BUF);
            const uint32_t a_lo = a_hi + A_BUF;
            const uint32_t b_hi = sbase + SM_B + cur * (2 * B_BUF);
            const uint32_t b_lo = b_hi + B_BUF;

            #pragma unroll
            for (int ks = 0; ks < 2; ks++) {
                uint32_t ah[2][4], al[2][4];
                #pragma unroll
                for (int mt = 0; mt < 2; mt++) {
                    const uint32_t ar = (arow0 + mt * 16) * ROWB + ks * 32 + aco;
                    ldsm_x4(ah[mt], a_hi + ar);
                    ldsm_x4(al[mt], a_lo + ar);
                }
                const uint32_t bh0 = b_hi + brow0 * ROWB + ks * 32 + bco;
                const uint32_t bl0 = b_lo + brow0 * ROWB + ks * 32 + bco;
                #pragma unroll
                for (int nt2 = 0; nt2 < 4; nt2++) {
                    uint32_t bh[4], bl[4];
                    ldsm_x4(bh, bh0 + nt2 * 16 * ROWB);
                    ldsm_x4(bl, bl0 + nt2 * 16 * ROWB);
                    #pragma unroll
                    for (int mt = 0; mt < 2; mt++) {
                        float* a0 = acc[mt * 8 + 2 * nt2];
                        float* a1 = acc[mt * 8 + 2 * nt2 + 1];
                        mma_bf16(a0, ah[mt], bh);
                        mma_bf16(a0, ah[mt], bl);
                        mma_bf16(a0, al[mt], bh);
                        mma_bf16(a1, ah[mt], bh + 2);
                        mma_bf16(a1, ah[mt], bl + 2);
                        mma_bf16(a1, al[mt], bh + 2);
                    }
                }
            }
            __syncthreads();   // all warps done reading `cur` before refill
        }

        // ---- epilogue: tanh + va-weighted reduction over this kc's slab ----
        #pragma unroll
        for (int mt = 0; mt < 2; mt++) {
            float p0 = 0.f, p1 = 0.f;
            #pragma unroll
            for (int nt = 0; nt < 8; nt++) {
                const int k = kc * KC + nw * 64 + nt * 8 + (lane & 3) * 2;
                const float c0 = s_c[k], c1 = s_c[k + 1];
                const float v0 = s_va[k], v1 = s_va[k + 1];
                const float* a = acc[mt * 8 + nt];
                p0 += v0 * tanhf(a[0] + c0);
                p0 += v1 * tanhf(a[1] + c1);
                p1 += v0 * tanhf(a[2] + c0);
                p1 += v1 * tanhf(a[3] + c1);
            }
            p0 += __shfl_xor_sync(0xffffffffu, p0, 1);
            p0 += __shfl_xor_sync(0xffffffffu, p0, 2);
            p1 += __shfl_xor_sync(0xffffffffu, p1, 1);
            p1 += __shfl_xor_sync(0xffffffffu, p1, 2);
            sc[mt * 2]     += p0;
            sc[mt * 2 + 1] += p1;
        }
    }

    // ---- combine the two N-warp groups and write scores ----
    if ((lane & 3) == 0) {
        const int r = lane >> 2;   // 0..7
        #pragma unroll
        for (int mt = 0; mt < 2; mt++) {
            const int row = mw * 32 + mt * 16 + r;
            s_red[nw * 128 + row]     = sc[mt * 2];
            s_red[nw * 128 + row + 8] = sc[mt * 2 + 1];
        }
    }
    __syncthreads();
    if (tid < 128) {
        const int l = l0 + tid;
        float s = s_red[tid] + s_red[128 + tid] + va_b[0];
        if (mask[b * Lsz + l]) s = -INFINITY;
        g_scores[b * Lsz + l] = s;
    }
}

// ---------------------------------------------------------------------------
// Kernel C: softmax over L per batch
// ---------------------------------------------------------------------------
__global__ __launch_bounds__(256) void softmax_kernel()
{
    __shared__ float red[256];
    const int b = blockIdx.x;
    const int tid = threadIdx.x;

    float mx = -INFINITY;
    for (int l = tid; l < Lsz; l += 256) mx = fmaxf(mx, g_scores[b * Lsz + l]);
    red[tid] = mx;
    __syncthreads();
    for (int s = 128; s; s >>= 1) {
        if (tid < s) red[tid] = fmaxf(red[tid], red[tid + s]);
        __syncthreads();
    }
    mx = red[0];
    __syncthreads();

    float sum = 0.f;
    for (int l = tid; l < Lsz; l += 256) {
        const float e = expf(g_scores[b * Lsz + l] - mx);
        g_weights[b * Lsz + l] = e;
        sum += e;
    }
    red[tid] = sum;
    __syncthreads();
    for (int s = 128; s; s >>= 1) {
        if (tid < s) red[tid] += red[tid + s];
        __syncthreads();
    }
    const float inv = 1.f / red[0];
    for (int l = tid; l < Lsz; l += 256) g_weights[b * Lsz + l] *= inv;
}

// ---------------------------------------------------------------------------
// Kernel D: partial contexts
// ---------------------------------------------------------------------------
__global__ __launch_bounds__(256) void context_kernel(const float* __restrict__ keys)
{
    __shared__ float wsh[256];
    const int s = blockIdx.x;
    const int b = blockIdx.y;
    const int t = threadIdx.x;

    wsh[t] = g_weights[b * Lsz + s * 256 + t];
    __syncthreads();

    float4 acc = make_float4(0.f, 0.f, 0.f, 0.f);
    const float* kb = keys + ((size_t)b * Lsz + s * 256) * Hsz;
    #pragma unroll 4
    for (int l = 0; l < 256; l++) {
        const float w = wsh[l];
        float4 kv = *(const float4*)(kb + (size_t)l * Hsz + t * 4);
        acc.x += w * kv.x;
        acc.y += w * kv.y;
        acc.z += w * kv.z;
        acc.w += w * kv.w;
    }
    *(float4*)&g_part[s][b * Hsz + t * 4] = acc;
}

// ---------------------------------------------------------------------------
// Kernel E: reduce partials
// ---------------------------------------------------------------------------
__global__ __launch_bounds__(256) void reduce_kernel(float* __restrict__ out)
{
    const int i = blockIdx.x * 256 + threadIdx.x;
    float s = 0.f;
    #pragma unroll
    for (int p = 0; p < 8; p++) s += g_part[p][i];
    out[i] = s;
}

// ---------------------------------------------------------------------------
extern "C" void kernel_launch(void* const* d_in, const int* in_sizes, int n_in,
                              void* d_out, int out_size)
{
    const float* query = (const float*)d_in[0];
    const float* keys  = (const float*)d_in[1];
    const unsigned char* mask = (const unsigned char*)d_in[2];
    const float* wa_w = (const float*)d_in[3];
    const float* wa_b = (const float*)d_in[4];
    const float* ua_w = (const float*)d_in[5];
    const float* ua_b = (const float*)d_in[6];
    const float* va_w = (const float*)d_in[7];
    const float* va_b = (const float*)d_in[8];
    float* out = (float*)d_out;

    cudaFuncSetAttribute(scores_mma_kernel,
                         cudaFuncAttributeMaxDynamicSharedMemorySize, SM_TOTAL);

    presplit_uw_kernel<<<(Hsz * Hsz / 4) / 256, 256>>>(ua_w);
    presplit_keys_kernel<<<(int)(((size_t)Bsz * Lsz * Hsz / 4) / 256), 256>>>(keys);
    wq_kernel<<<Bsz, 256>>>(query, wa_w, wa_b);
    scores_mma_kernel<<<dim3(Lsz / TM, Bsz), 256, SM_TOTAL>>>(
        ua_b, va_w, va_b, mask);
    softmax_kernel<<<Bsz, 256>>>();
    context_kernel<<<dim3(8, Bsz), 256>>>(keys);
    reduce_kernel<<<(Bsz * Hsz) / 256, 256>>>(out);
}

// round 15
// speedup vs baseline: 1.0838x; 1.0110x over previous
#include <cuda_runtime.h>
#include <cuda_bf16.h>
#include <math.h>
#include <stdint.h>

// Problem constants
constexpr int Bsz = 32;
constexpr int Lsz = 2048;
constexpr int Hsz = 1024;

// Scratch
__device__ float g_wq[Bsz * Hsz];
__device__ float g_scores[Bsz * Lsz];
__device__ float g_weights[Bsz * Lsz];
__device__ float g_part[8][Bsz * Hsz];
__device__ __align__(16) __nv_bfloat16 g_uw_hi[Hsz * Hsz];        // ua_w hi
__device__ __align__(16) __nv_bfloat16 g_uw_lo[Hsz * Hsz];        // ua_w lo
__device__ __align__(16) __nv_bfloat16 g_k_hi[Bsz * Lsz * Hsz];   // keys hi (128MB)
__device__ __align__(16) __nv_bfloat16 g_k_lo[Bsz * Lsz * Hsz];   // keys lo (128MB)

// ---------------------------------------------------------------------------
// mma.sync / ldmatrix / cp.async helpers
// ---------------------------------------------------------------------------
__device__ __forceinline__ uint32_t smem_to_u32(const void* p) {
    uint32_t a;
    asm("{ .reg .u64 t; cvta.to.shared.u64 t, %1; cvt.u32.u64 %0, t; }" : "=r"(a) : "l"(p));
    return a;
}
__device__ __forceinline__ void ldsm_x4(uint32_t* r, uint32_t addr) {
    asm volatile("ldmatrix.sync.aligned.m8n8.x4.shared.b16 {%0,%1,%2,%3}, [%4];"
        : "=r"(r[0]), "=r"(r[1]), "=r"(r[2]), "=r"(r[3]) : "r"(addr));
}
__device__ __forceinline__ void mma_bf16(float* c, const uint32_t* a, const uint32_t* b) {
    asm volatile("mma.sync.aligned.m16n8k16.row.col.f32.bf16.bf16.f32 "
        "{%0,%1,%2,%3}, {%4,%5,%6,%7}, {%8,%9}, {%0,%1,%2,%3};"
        : "+f"(c[0]), "+f"(c[1]), "+f"(c[2]), "+f"(c[3])
        : "r"(a[0]), "r"(a[1]), "r"(a[2]), "r"(a[3]), "r"(b[0]), "r"(b[1]));
}
__device__ __forceinline__ void cp16(uint32_t dst, const void* src) {
    asm volatile("cp.async.cg.shared.global [%0], [%1], 16;" :: "r"(dst), "l"(src));
}
#define CP_COMMIT() asm volatile("cp.async.commit_group;" ::: "memory")
#define CP_WAIT(n)  asm volatile("cp.async.wait_group %0;" :: "n"(n) : "memory")

// ---------------------------------------------------------------------------
// Split helpers
// ---------------------------------------------------------------------------
__device__ __forceinline__ void split4(float4 v, uint2& hu, uint2& lu) {
    __nv_bfloat16 h0 = __float2bfloat16_rn(v.x);
    __nv_bfloat16 h1 = __float2bfloat16_rn(v.y);
    __nv_bfloat16 h2 = __float2bfloat16_rn(v.z);
    __nv_bfloat16 h3 = __float2bfloat16_rn(v.w);
    __nv_bfloat16 l0 = __float2bfloat16_rn(v.x - __bfloat162float(h0));
    __nv_bfloat16 l1 = __float2bfloat16_rn(v.y - __bfloat162float(h1));
    __nv_bfloat16 l2 = __float2bfloat16_rn(v.z - __bfloat162float(h2));
    __nv_bfloat16 l3 = __float2bfloat16_rn(v.w - __bfloat162float(h3));
    __nv_bfloat162 ha = __halves2bfloat162(h0, h1), hb = __halves2bfloat162(h2, h3);
    __nv_bfloat162 la = __halves2bfloat162(l0, l1), lb = __halves2bfloat162(l2, l3);
    hu = make_uint2(*reinterpret_cast<uint32_t*>(&ha), *reinterpret_cast<uint32_t*>(&hb));
    lu = make_uint2(*reinterpret_cast<uint32_t*>(&la), *reinterpret_cast<uint32_t*>(&lb));
}

__global__ __launch_bounds__(256) void presplit_uw_kernel(const float* __restrict__ ua_w)
{
    const int i4 = blockIdx.x * 256 + threadIdx.x;
    uint2 hu, lu;
    split4(((const float4*)ua_w)[i4], hu, lu);
    ((uint2*)g_uw_hi)[i4] = hu;
    ((uint2*)g_uw_lo)[i4] = lu;
}

__global__ __launch_bounds__(256) void presplit_keys_kernel(const float* __restrict__ keys)
{
    const size_t i4 = (size_t)blockIdx.x * 256 + threadIdx.x;
    uint2 hu, lu;
    split4(((const float4*)keys)[i4], hu, lu);
    ((uint2*)g_k_hi)[i4] = hu;
    ((uint2*)g_k_lo)[i4] = lu;
}

// ---------------------------------------------------------------------------
// Kernel A: wq[b,k] = query[b,:]·wa_w[k,:] + wa_b[k]
// ---------------------------------------------------------------------------
__global__ __launch_bounds__(256) void wq_kernel(
    const float* __restrict__ query, const float* __restrict__ wa_w,
    const float* __restrict__ wa_b)
{
    __shared__ __align__(16) float qs[Hsz];
    const int b = blockIdx.x;
    for (int i = threadIdx.x; i < Hsz / 4; i += blockDim.x)
        ((float4*)qs)[i] = ((const float4*)(query + (size_t)b * Hsz))[i];
    __syncthreads();

    const int warp = threadIdx.x >> 5;
    const int lane = threadIdx.x & 31;
    for (int k = warp; k < Hsz; k += 8) {
        const float4* wrow = (const float4*)(wa_w + (size_t)k * Hsz);
        float sum = 0.f;
        #pragma unroll
        for (int i = 0; i < 8; i++) {
            float4 wv = wrow[lane + 32 * i];
            float4 qv = ((const float4*)qs)[lane + 32 * i];
            sum += wv.x * qv.x + wv.y * qv.y + wv.z * qv.z + wv.w * qv.w;
        }
        #pragma unroll
        for (int off = 16; off; off >>= 1)
            sum += __shfl_down_sync(0xffffffffu, sum, off);
        if (lane == 0) g_wq[b * Hsz + k] = sum + wa_b[k];
    }
}

// ---------------------------------------------------------------------------
// Kernel B: fused scores via bf16x3 mma.sync, cp.async staging.
// 2D warp tiling (4 M-warps x 2 N-warps, warp tile M32 x N64).
// MMA issue order: term-major round-robin over 4 accumulators ->
// RAW dependency distance 4 (was 1) to cover HMMA latency.
// ---------------------------------------------------------------------------
constexpr int TM = 128;
constexpr int KC = 128;
constexpr int HC = 32;
constexpr int NHC = Hsz / HC;   // 32
constexpr int ROWB = 80;        // 64B data + 16B pad -> conflict-free ldsm

constexpr int SM_C   = 0;                     // wq+ua_b: 4KB
constexpr int SM_VA  = 4096;                  // va_w:    4KB
constexpr int SM_A   = 8192;                  // A: [buf][hi/lo][128*80]
constexpr int A_BUF  = TM * ROWB;             // 10240
constexpr int SM_B   = SM_A + 4 * A_BUF;      // 49152; B: [buf][hi/lo][128*80]
constexpr int B_BUF  = KC * ROWB;             // 10240
constexpr int SM_RED = SM_B + 4 * B_BUF;      // 90112; cross-warp: 2*128 f32
constexpr int SM_TOTAL = SM_RED + 1024;       // 91136  (2 CTAs fit in 228KB)

__global__ __launch_bounds__(256, 2) void scores_mma_kernel(
    const float* __restrict__ ua_b,
    const float* __restrict__ va_w,
    const float* __restrict__ va_b,
    const unsigned char* __restrict__ mask)
{
    extern __shared__ __align__(128) char smem[];
    const uint32_t sbase = smem_to_u32(smem);
    const int tid  = threadIdx.x;
    const int lane = tid & 31;
    const int w    = tid >> 5;
    const int mw   = w & 3;          // M-warp group: rows [mw*32, mw*32+32)
    const int nw   = w >> 2;         // N-warp group: cols [nw*64, nw*64+64)
    const int b    = blockIdx.y;
    const int l0   = blockIdx.x * TM;

    float* s_c   = (float*)(smem + SM_C);
    float* s_va  = (float*)(smem + SM_VA);
    float* s_red = (float*)(smem + SM_RED);
    for (int i = tid; i < Hsz; i += 256) {
        s_c[i]  = g_wq[b * Hsz + i] + ua_b[i];
        s_va[i] = va_w[i];
    }

    const __nv_bfloat16* kHi = g_k_hi + ((size_t)b * Lsz + l0) * Hsz;
    const __nv_bfloat16* kLo = g_k_lo + ((size_t)b * Lsz + l0) * Hsz;

    float sc[4] = {0.f, 0.f, 0.f, 0.f};  // [mt*2 + half] row-group partials

    // ldmatrix per-lane addressing
    const int arow0 = mw * 32 + (lane & 15);           // A row, m-tile 0 (+16 for mt1)
    const int aco   = (lane >> 4) << 4;                // A k-half byte offset
    const int bn    = (lane & 7) | ((lane >> 4) << 3); // B row 0..15 (two n8 tiles)
    const int bco   = ((lane >> 3) & 1) << 4;          // B k-half byte offset
    const int brow0 = nw * 64 + bn;                    // B row base for this N-warp

    // cp.async staging indices
    const int a_row = tid >> 2;     // 0..63, +p*64
    const int a_c   = tid & 3;

    #pragma unroll 1
    for (int kc = 0; kc < 8; kc++) {
        float acc[16][4];   // [mt*8 + nt][4]
        #pragma unroll
        for (int nt = 0; nt < 16; nt++)
            #pragma unroll
            for (int j = 0; j < 4; j++) acc[nt][j] = 0.f;

        // ---- issue chunk 0 into buffer 0 ----
        {
            const uint32_t A0 = sbase + SM_A;
            const uint32_t B0 = sbase + SM_B;
            #pragma unroll
            for (int p = 0; p < 2; p++) {   // A hi/lo: 128 rows
                const int row = a_row + p * 64;
                cp16(A0 + row * ROWB + a_c * 16,
                     kHi + (size_t)row * Hsz + a_c * 8);
                cp16(A0 + A_BUF + row * ROWB + a_c * 16,
                     kLo + (size_t)row * Hsz + a_c * 8);
            }
            #pragma unroll
            for (int p = 0; p < 2; p++) {   // B hi/lo: 128 rows
                const int row = a_row + p * 64;
                cp16(B0 + row * ROWB + a_c * 16,
                     g_uw_hi + (size_t)(kc * KC + row) * Hsz + a_c * 8);
                cp16(B0 + B_BUF + row * ROWB + a_c * 16,
                     g_uw_lo + (size_t)(kc * KC + row) * Hsz + a_c * 8);
            }
            CP_COMMIT();
        }

        #pragma unroll 1
        for (int hc = 0; hc < NHC; hc++) {
            const int cur = hc & 1, nxt = cur ^ 1;
            const bool pf = (hc + 1 < NHC);

            // ---- issue next chunk into other buffer ----
            if (pf) {
                const int h0 = (hc + 1) * HC;
                const uint32_t An = sbase + SM_A + nxt * (2 * A_BUF);
                const uint32_t Bn = sbase + SM_B + nxt * (2 * B_BUF);
                #pragma unroll
                for (int p = 0; p < 2; p++) {
                    const int row = a_row + p * 64;
                    cp16(An + row * ROWB + a_c * 16,
                         kHi + (size_t)row * Hsz + h0 + a_c * 8);
                    cp16(An + A_BUF + row * ROWB + a_c * 16,
                         kLo + (size_t)row * Hsz + h0 + a_c * 8);
                }
                #pragma unroll
                for (int p = 0; p < 2; p++) {
                    const int row = a_row + p * 64;
                    cp16(Bn + row * ROWB + a_c * 16,
                         g_uw_hi + (size_t)(kc * KC + row) * Hsz + h0 + a_c * 8);
                    cp16(Bn + B_BUF + row * ROWB + a_c * 16,
                         g_uw_lo + (size_t)(kc * KC + row) * Hsz + h0 + a_c * 8);
                }
                CP_COMMIT();
                CP_WAIT(1);
            } else {
                CP_WAIT(0);
            }
            __syncthreads();   // chunk `cur` visible to all warps

            // ---- MMA block on current buffer (warp tile M32 x N64) ----
            const uint32_t a_hi = sbase + SM_A + cur * (2 * A_BUF);
            const uint32_t a_lo = a_hi + A_BUF;
            const uint32_t b_hi = sbase + SM_B + cur * (2 * B_BUF);
            const uint32_t b_lo = b_hi + B_BUF;

            #pragma unroll
            for (int ks = 0; ks < 2; ks++) {
                uint32_t ah[2][4], al[2][4];
                #pragma unroll
                for (int mt = 0; mt < 2; mt++) {
                    const uint32_t ar = (arow0 + mt * 16) * ROWB + ks * 32 + aco;
                    ldsm_x4(ah[mt], a_hi + ar);
                    ldsm_x4(al[mt], a_lo + ar);
                }
                const uint32_t bh0 = b_hi + brow0 * ROWB + ks * 32 + bco;
                const uint32_t bl0 = b_lo + brow0 * ROWB + ks * 32 + bco;
                #pragma unroll
                for (int nt2 = 0; nt2 < 4; nt2++) {
                    uint32_t bh[4], bl[4];
                    ldsm_x4(bh, bh0 + nt2 * 16 * ROWB);
                    ldsm_x4(bl, bl0 + nt2 * 16 * ROWB);
                    float* a00 = acc[0 * 8 + 2 * nt2];      // mt0, n-half 0
                    float* a01 = acc[0 * 8 + 2 * nt2 + 1];  // mt0, n-half 1
                    float* a10 = acc[1 * 8 + 2 * nt2];      // mt1, n-half 0
                    float* a11 = acc[1 * 8 + 2 * nt2 + 1];  // mt1, n-half 1
                    // term 1: hi*hi  (RR over 4 accumulators -> dep distance 4)
                    mma_bf16(a00, ah[0], bh);
                    mma_bf16(a01, ah[0], bh + 2);
                    mma_bf16(a10, ah[1], bh);
                    mma_bf16(a11, ah[1], bh + 2);
                    // term 2: hi*lo
                    mma_bf16(a00, ah[0], bl);
                    mma_bf16(a01, ah[0], bl + 2);
                    mma_bf16(a10, ah[1], bl);
                    mma_bf16(a11, ah[1], bl + 2);
                    // term 3: lo*hi
                    mma_bf16(a00, al[0], bh);
                    mma_bf16(a01, al[0], bh + 2);
                    mma_bf16(a10, al[1], bh);
                    mma_bf16(a11, al[1], bh + 2);
                }
            }
            __syncthreads();   // all warps done reading `cur` before refill
        }

        // ---- epilogue: tanh + va-weighted reduction over this kc's slab ----
        #pragma unroll
        for (int mt = 0; mt < 2; mt++) {
            float p0 = 0.f, p1 = 0.f;
            #pragma unroll
            for (int nt = 0; nt < 8; nt++) {
                const int k = kc * KC + nw * 64 + nt * 8 + (lane & 3) * 2;
                const float c0 = s_c[k], c1 = s_c[k + 1];
                const float v0 = s_va[k], v1 = s_va[k + 1];
                const float* a = acc[mt * 8 + nt];
                p0 += v0 * tanhf(a[0] + c0);
                p0 += v1 * tanhf(a[1] + c1);
                p1 += v0 * tanhf(a[2] + c0);
                p1 += v1 * tanhf(a[3] + c1);
            }
            p0 += __shfl_xor_sync(0xffffffffu, p0, 1);
            p0 += __shfl_xor_sync(0xffffffffu, p0, 2);
            p1 += __shfl_xor_sync(0xffffffffu, p1, 1);
            p1 += __shfl_xor_sync(0xffffffffu, p1, 2);
            sc[mt * 2]     += p0;
            sc[mt * 2 + 1] += p1;
        }
    }

    // ---- combine the two N-warp groups and write scores ----
    if ((lane & 3) == 0) {
        const int r = lane >> 2;   // 0..7
        #pragma unroll
        for (int mt = 0; mt < 2; mt++) {
            const int row = mw * 32 + mt * 16 + r;
            s_red[nw * 128 + row]     = sc[mt * 2];
            s_red[nw * 128 + row + 8] = sc[mt * 2 + 1];
        }
    }
    __syncthreads();
    if (tid < 128) {
        const int l = l0 + tid;
        float s = s_red[tid] + s_red[128 + tid] + va_b[0];
        if (mask[b * Lsz + l]) s = -INFINITY;
        g_scores[b * Lsz + l] = s;
    }
}

// ---------------------------------------------------------------------------
// Kernel C: softmax over L per batch
// ---------------------------------------------------------------------------
__global__ __launch_bounds__(256) void softmax_kernel()
{
    __shared__ float red[256];
    const int b = blockIdx.x;
    const int tid = threadIdx.x;

    float mx = -INFINITY;
    for (int l = tid; l < Lsz; l += 256) mx = fmaxf(mx, g_scores[b * Lsz + l]);
    red[tid] = mx;
    __syncthreads();
    for (int s = 128; s; s >>= 1) {
        if (tid < s) red[tid] = fmaxf(red[tid], red[tid + s]);
        __syncthreads();
    }
    mx = red[0];
    __syncthreads();

    float sum = 0.f;
    for (int l = tid; l < Lsz; l += 256) {
        const float e = expf(g_scores[b * Lsz + l] - mx);
        g_weights[b * Lsz + l] = e;
        sum += e;
    }
    red[tid] = sum;
    __syncthreads();
    for (int s = 128; s; s >>= 1) {
        if (tid < s) red[tid] += red[tid + s];
        __syncthreads();
    }
    const float inv = 1.f / red[0];
    for (int l = tid; l < Lsz; l += 256) g_weights[b * Lsz + l] *= inv;
}

// ---------------------------------------------------------------------------
// Kernel D: partial contexts
// ---------------------------------------------------------------------------
__global__ __launch_bounds__(256) void context_kernel(const float* __restrict__ keys)
{
    __shared__ float wsh[256];
    const int s = blockIdx.x;
    const int b = blockIdx.y;
    const int t = threadIdx.x;

    wsh[t] = g_weights[b * Lsz + s * 256 + t];
    __syncthreads();

    float4 acc = make_float4(0.f, 0.f, 0.f, 0.f);
    const float* kb = keys + ((size_t)b * Lsz + s * 256) * Hsz;
    #pragma unroll 4
    for (int l = 0; l < 256; l++) {
        const float w = wsh[l];
        float4 kv = *(const float4*)(kb + (size_t)l * Hsz + t * 4);
        acc.x += w * kv.x;
        acc.y += w * kv.y;
        acc.z += w * kv.z;
        acc.w += w * kv.w;
    }
    *(float4*)&g_part[s][b * Hsz + t * 4] = acc;
}

// ---------------------------------------------------------------------------
// Kernel E: reduce partials
// ---------------------------------------------------------------------------
__global__ __launch_bounds__(256) void reduce_kernel(float* __restrict__ out)
{
    const int i = blockIdx.x * 256 + threadIdx.x;
    float s = 0.f;
    #pragma unroll
    for (int p = 0; p < 8; p++) s += g_part[p][i];
    out[i] = s;
}

// ---------------------------------------------------------------------------
extern "C" void kernel_launch(void* const* d_in, const int* in_sizes, int n_in,
                              void* d_out, int out_size)
{
    const float* query = (const float*)d_in[0];
    const float* keys  = (const float*)d_in[1];
    const unsigned char* mask = (const unsigned char*)d_in[2];
    const float* wa_w = (const float*)d_in[3];
    const float* wa_b = (const float*)d_in[4];
    const float* ua_w = (const float*)d_in[5];
    const float* ua_b = (const float*)d_in[6];
    const float* va_w = (const float*)d_in[7];
    const float* va_b = (const float*)d_in[8];
    float* out = (float*)d_out;

    cudaFuncSetAttribute(scores_mma_kernel,
                         cudaFuncAttributeMaxDynamicSharedMemorySize, SM_TOTAL);

    presplit_uw_kernel<<<(Hsz * Hsz / 4) / 256, 256>>>(ua_w);
    presplit_keys_kernel<<<(int)(((size_t)Bsz * Lsz * Hsz / 4) / 256), 256>>>(keys);
    wq_kernel<<<Bsz, 256>>>(query, wa_w, wa_b);
    scores_mma_kernel<<<dim3(Lsz / TM, Bsz), 256, SM_TOTAL>>>(
        ua_b, va_w, va_b, mask);
    softmax_kernel<<<Bsz, 256>>>();
    context_kernel<<<dim3(8, Bsz), 256>>>(keys);
    reduce_kernel<<<(Bsz * Hsz) / 256, 256>>>(out);
}